// round 2
// baseline (speedup 1.0000x reference)
#include <cuda_runtime.h>
#include <cuda_bf16.h>

// Problem: x[4096,8], sparse_grid[4096,8], chol_inv[4096,4096] (lower-tri), ls[8]
// k_star[i,j] = exp(-sum_d |x[i,d]-g[j,d]| / ls[d]);  phi = k_star @ chol_inv
// Output fp32 [4096, 4096].

#define N_PTS 4096
#define M_PTS 4096
#define DIMS 8

// 64 MB scratch for k_star (device global: allocation-guard-safe)
__device__ float g_kstar[(size_t)N_PTS * (size_t)M_PTS];

// ---------------------------------------------------------------------------
// Stage 1: k_star. One block per row i; 256 threads stride over j.
// grid rows are 32B (two float4) -> vectorized, L2-resident (128 KB total).
// ---------------------------------------------------------------------------
__global__ __launch_bounds__(256) void kstar_kernel(
    const float* __restrict__ x,
    const float* __restrict__ grid,
    const float* __restrict__ ls)
{
    const int i = blockIdx.x;
    __shared__ float xs[DIMS];
    __shared__ float rls[DIMS];
    if (threadIdx.x < DIMS) {
        xs[threadIdx.x]  = x[(size_t)i * DIMS + threadIdx.x];
        rls[threadIdx.x] = 1.0f / ls[threadIdx.x];
    }
    __syncthreads();

    float xr[DIMS], rl[DIMS];
#pragma unroll
    for (int d = 0; d < DIMS; d++) { xr[d] = xs[d]; rl[d] = rls[d]; }

    const float4* g4 = reinterpret_cast<const float4*>(grid);
    float* out = g_kstar + (size_t)i * M_PTS;

    for (int j = threadIdx.x; j < M_PTS; j += blockDim.x) {
        float4 a = g4[2 * j];
        float4 b = g4[2 * j + 1];
        float s = fabsf(xr[0] - a.x) * rl[0]
                + fabsf(xr[1] - a.y) * rl[1]
                + fabsf(xr[2] - a.z) * rl[2]
                + fabsf(xr[3] - a.w) * rl[3]
                + fabsf(xr[4] - b.x) * rl[4]
                + fabsf(xr[5] - b.y) * rl[5]
                + fabsf(xr[6] - b.z) * rl[6]
                + fabsf(xr[7] - b.w) * rl[7];
        out[j] = __expf(-s);
    }
}

// ---------------------------------------------------------------------------
// Stage 2: C = k_star @ chol_inv, exploiting lower-triangular B:
// for output columns [col0, col0+BN), only k >= col0 contributes.
// Classic 128x128x16 register-tiled SGEMM, 256 threads, 8x8 microtile.
// ---------------------------------------------------------------------------
#define BM 128
#define BN 128
#define BK 16
#define TM 8
#define TN 8

__global__ __launch_bounds__(256) void sgemm_tril(
    const float* __restrict__ B,   // chol_inv [K=4096, N=4096] row-major
    float* __restrict__ C)
{
    const int K = M_PTS;
    const int NC = M_PTS;

    const int bx = blockIdx.x;   // column block
    const int by = blockIdx.y;   // row block

    __shared__ float As[BK][BM];   // transposed A tile
    __shared__ float Bs[BK][BN];

    const float* A = g_kstar;
    const int row0 = by * BM;
    const int col0 = bx * BN;
    const int k0   = col0;         // triangular: chol_inv[k, j] == 0 for k < j

    const int tid  = threadIdx.x;
    // A tile loader: 128 rows x 16 cols, float4 per thread, 2 passes of 64 rows
    const int aRow = tid / 4;            // 0..63
    const int aCol = (tid % 4) * 4;      // 0,4,8,12
    // B tile loader: 16 rows x 128 cols, float4 per thread, 2 passes of 8 rows
    const int bRow = tid / 32;           // 0..7
    const int bCol = (tid % 32) * 4;     // 0..124

    const int tRow = (tid / 16) * TM;    // 0..120
    const int tCol = (tid % 16) * TN;    // 0..120

    float acc[TM][TN] = {};
    float regM[TM], regN[TN];

    for (int k = k0; k < K; k += BK) {
#pragma unroll
        for (int off = 0; off < BM; off += 64) {
            float4 v = *reinterpret_cast<const float4*>(
                A + (size_t)(row0 + aRow + off) * K + k + aCol);
            As[aCol + 0][aRow + off] = v.x;
            As[aCol + 1][aRow + off] = v.y;
            As[aCol + 2][aRow + off] = v.z;
            As[aCol + 3][aRow + off] = v.w;
        }
#pragma unroll
        for (int off = 0; off < BK; off += 8) {
            float4 v = *reinterpret_cast<const float4*>(
                B + (size_t)(k + bRow + off) * NC + col0 + bCol);
            *reinterpret_cast<float4*>(&Bs[bRow + off][bCol]) = v;
        }
        __syncthreads();

#pragma unroll
        for (int kk = 0; kk < BK; kk++) {
            float4 m0 = *reinterpret_cast<const float4*>(&As[kk][tRow]);
            float4 m1 = *reinterpret_cast<const float4*>(&As[kk][tRow + 4]);
            regM[0] = m0.x; regM[1] = m0.y; regM[2] = m0.z; regM[3] = m0.w;
            regM[4] = m1.x; regM[5] = m1.y; regM[6] = m1.z; regM[7] = m1.w;
            float4 n0 = *reinterpret_cast<const float4*>(&Bs[kk][tCol]);
            float4 n1 = *reinterpret_cast<const float4*>(&Bs[kk][tCol + 4]);
            regN[0] = n0.x; regN[1] = n0.y; regN[2] = n0.z; regN[3] = n0.w;
            regN[4] = n1.x; regN[5] = n1.y; regN[6] = n1.z; regN[7] = n1.w;
#pragma unroll
            for (int i = 0; i < TM; i++)
#pragma unroll
                for (int j = 0; j < TN; j++)
                    acc[i][j] += regM[i] * regN[j];
        }
        __syncthreads();
    }

#pragma unroll
    for (int i = 0; i < TM; i++) {
#pragma unroll
        for (int j = 0; j < TN; j += 4) {
            float4 v = make_float4(acc[i][j], acc[i][j + 1],
                                   acc[i][j + 2], acc[i][j + 3]);
            *reinterpret_cast<float4*>(
                C + (size_t)(row0 + tRow + i) * NC + col0 + tCol + j) = v;
        }
    }
}

// ---------------------------------------------------------------------------
extern "C" void kernel_launch(void* const* d_in, const int* in_sizes, int n_in,
                              void* d_out, int out_size)
{
    const float* x    = (const float*)d_in[0];   // [4096, 8]
    const float* grid = (const float*)d_in[1];   // [4096, 8]
    const float* chol = (const float*)d_in[2];   // [4096, 4096]
    const float* ls   = (const float*)d_in[3];   // [8]
    float* out = (float*)d_out;                  // [4096, 4096]

    kstar_kernel<<<N_PTS, 256>>>(x, grid, ls);

    dim3 g(M_PTS / BN, N_PTS / BM);
    sgemm_tril<<<g, 256>>>(chol, out);
}

// round 4
// speedup vs baseline: 2.4302x; 2.4302x over previous
#include <cuda_runtime.h>
#include <cuda_bf16.h>
#include <cstdint>

// phi = exp(-sum_d |x[i,d]-g[j,d]|/ls[d]) @ chol_inv (lower-tri), [4096,4096] fp32.
// Engine: mma.sync bf16 (HMMA) with hi/lo split x3, triangular K-start.

#define N_PTS 4096
#define M_PTS 4096
#define DIMS 8

__device__ __nv_bfloat16 g_Ah[(size_t)N_PTS * M_PTS];
__device__ __nv_bfloat16 g_Al[(size_t)N_PTS * M_PTS];
__device__ __nv_bfloat16 g_Bh[(size_t)M_PTS * M_PTS];  // B^T: [j, k]
__device__ __nv_bfloat16 g_Bl[(size_t)M_PTS * M_PTS];

__device__ __forceinline__ uint32_t smem_u32(const void* p) {
    uint32_t a;
    asm("{ .reg .u64 t; cvta.to.shared.u64 t, %1; cvt.u32.u64 %0, t; }" : "=r"(a) : "l"(p));
    return a;
}

// ---------------------------------------------------------------------------
// Stage 1: k_star rows -> bf16 hi/lo
// ---------------------------------------------------------------------------
__global__ __launch_bounds__(256) void kstar_split(
    const float* __restrict__ x, const float* __restrict__ grid,
    const float* __restrict__ ls)
{
    const int i = blockIdx.x;
    __shared__ float xs[DIMS], rls[DIMS];
    if (threadIdx.x < DIMS) {
        xs[threadIdx.x]  = x[(size_t)i * DIMS + threadIdx.x];
        rls[threadIdx.x] = 1.0f / ls[threadIdx.x];
    }
    __syncthreads();
    float xr[DIMS], rl[DIMS];
#pragma unroll
    for (int d = 0; d < DIMS; d++) { xr[d] = xs[d]; rl[d] = rls[d]; }

    const float4* g4 = reinterpret_cast<const float4*>(grid);
    __nv_bfloat16* oh = g_Ah + (size_t)i * M_PTS;
    __nv_bfloat16* ol = g_Al + (size_t)i * M_PTS;

    for (int j = threadIdx.x; j < M_PTS; j += blockDim.x) {
        float4 a = g4[2 * j];
        float4 b = g4[2 * j + 1];
        float s = fabsf(xr[0] - a.x) * rl[0] + fabsf(xr[1] - a.y) * rl[1]
                + fabsf(xr[2] - a.z) * rl[2] + fabsf(xr[3] - a.w) * rl[3]
                + fabsf(xr[4] - b.x) * rl[4] + fabsf(xr[5] - b.y) * rl[5]
                + fabsf(xr[6] - b.z) * rl[6] + fabsf(xr[7] - b.w) * rl[7];
        float e = __expf(-s);
        __nv_bfloat16 h = __float2bfloat16(e);
        float rem = e - __bfloat162float(h);
        oh[j] = h;
        ol[j] = __float2bfloat16(rem);
    }
}

// ---------------------------------------------------------------------------
// Stage 2: transpose chol -> B^T[j,k] bf16 hi/lo
// ---------------------------------------------------------------------------
__global__ __launch_bounds__(256) void transpose_split(const float* __restrict__ chol)
{
    __shared__ float t[32][33];
    const int tx = threadIdx.x, ty = threadIdx.y;   // (32, 8)
    const int j0 = blockIdx.x * 32, k0 = blockIdx.y * 32;
#pragma unroll
    for (int r = 0; r < 32; r += 8)
        t[ty + r][tx] = chol[(size_t)(k0 + ty + r) * M_PTS + j0 + tx];
    __syncthreads();
#pragma unroll
    for (int r = 0; r < 32; r += 8) {
        float v = t[tx][ty + r];
        __nv_bfloat16 h = __float2bfloat16(v);
        float rem = v - __bfloat162float(h);
        size_t o = (size_t)(j0 + ty + r) * M_PTS + k0 + tx;
        g_Bh[o] = h;
        g_Bl[o] = __float2bfloat16(rem);
    }
}

// ---------------------------------------------------------------------------
// Stage 3: HMMA GEMM. CTA tile 128x128, BK=32, 8 warps (warp tile 64x32),
// cp.async double-buffer, padded smem stride 40 elems (80B, conflict-free).
// ---------------------------------------------------------------------------
#define BK 32
#define KSTRIDE 40                              // padded elems per row
#define TILE_B (128 * KSTRIDE * 2)              // 10240 bytes per tile
#define BUF_B (4 * TILE_B)                      // Ah, Al, Bh, Bl = 40960
#define SMEM_B (2 * BUF_B)                      // 81920

__device__ __forceinline__ void ldm4(uint32_t* r, uint32_t addr) {
    asm volatile("ldmatrix.sync.aligned.m8n8.x4.shared.b16 {%0,%1,%2,%3}, [%4];"
                 : "=r"(r[0]), "=r"(r[1]), "=r"(r[2]), "=r"(r[3]) : "r"(addr));
}
__device__ __forceinline__ void mma_bf16(float* c, const uint32_t* a, const uint32_t* b) {
    asm volatile(
        "mma.sync.aligned.m16n8k16.row.col.f32.bf16.bf16.f32 "
        "{%0,%1,%2,%3}, {%4,%5,%6,%7}, {%8,%9}, {%0,%1,%2,%3};"
        : "+f"(c[0]), "+f"(c[1]), "+f"(c[2]), "+f"(c[3])
        : "r"(a[0]), "r"(a[1]), "r"(a[2]), "r"(a[3]), "r"(b[0]), "r"(b[1]));
}
__device__ __forceinline__ void cpasync16(uint32_t saddr, const void* gaddr) {
    asm volatile("cp.async.cg.shared.global [%0], [%1], 16;" :: "r"(saddr), "l"(gaddr));
}

__device__ __forceinline__ void issue_chunk(uint32_t buf, int row0, int col0, int k,
                                            int tid)
{
    const __nv_bfloat16* srcs[4] = {
        g_Ah + (size_t)row0 * M_PTS, g_Al + (size_t)row0 * M_PTS,
        g_Bh + (size_t)col0 * M_PTS, g_Bl + (size_t)col0 * M_PTS };
#pragma unroll
    for (int t = 0; t < 4; ++t) {
        uint32_t sb = buf + t * TILE_B;
        const __nv_bfloat16* src = srcs[t];
#pragma unroll
        for (int p = 0; p < 2; ++p) {
            int idx = p * 256 + tid;          // 512 x 16B per tile
            int row = idx >> 2;
            int seg = idx & 3;                // 4 x 16B = 32 bf16 per row
            cpasync16(sb + row * (KSTRIDE * 2) + seg * 16,
                      src + (size_t)row * M_PTS + k + seg * 8);
        }
    }
}

__global__ __launch_bounds__(256, 1) void gemm_hmma(float* __restrict__ C)
{
    extern __shared__ char smem[];
    const uint32_t sb = smem_u32(smem);
    const int tid = threadIdx.x;
    const int lane = tid & 31, wid = tid >> 5;
    const int wm = wid >> 2;                  // 0..1  (64-row slabs)
    const int wn = wid & 3;                   // 0..3  (32-col slabs)

    const int row0 = blockIdx.y * 128;
    const int col0 = blockIdx.x * 128;
    const int k0 = col0;                      // triangular skip
    const int nchunk = (M_PTS - k0) / BK;     // >= 4

    float acc[4][4][4];
#pragma unroll
    for (int i = 0; i < 4; ++i)
#pragma unroll
        for (int j = 0; j < 4; ++j)
#pragma unroll
            for (int q = 0; q < 4; ++q) acc[i][j][q] = 0.0f;

    // ldmatrix lane addressing
    const int lr = lane & 7, lsel = lane >> 3;
    // A: matrices (m0-7,k0)(m8-15,k0)(m0-7,k8)(m8-15,k8)
    const int a_row_base = wm * 64 + lr + (lsel & 1) * 8;
    const int a_col_base = (lsel >> 1) * 8;
    // B: matrices (n0-7,k0)(n0-7,k8)(n8-15,k0)(n8-15,k8)
    const int b_row_base = wn * 32 + (lsel >> 1) * 8 + lr;
    const int b_col_base = (lsel & 1) * 8;

    issue_chunk(sb, row0, col0, k0, tid);
    asm volatile("cp.async.commit_group;");
    if (nchunk > 1) issue_chunk(sb + BUF_B, row0, col0, k0 + BK, tid);
    asm volatile("cp.async.commit_group;");

    for (int c = 0; c < nchunk; ++c) {
        asm volatile("cp.async.wait_group 1;");
        __syncthreads();
        const uint32_t buf = sb + (c & 1) * BUF_B;
        const uint32_t Ah = buf, Al = buf + TILE_B;
        const uint32_t Bh = buf + 2 * TILE_B, Bl = buf + 3 * TILE_B;

#pragma unroll
        for (int ks = 0; ks < 2; ++ks) {
            const int kel = ks * 16;
            uint32_t ah[4][4], al[4][4], bh[2][4], bl[2][4];
#pragma unroll
            for (int i = 0; i < 4; ++i) {
                uint32_t off = (a_row_base + i * 16) * (KSTRIDE * 2)
                             + (kel + a_col_base) * 2;
                ldm4(ah[i], Ah + off);
                ldm4(al[i], Al + off);
            }
#pragma unroll
            for (int jp = 0; jp < 2; ++jp) {
                uint32_t off = (b_row_base + jp * 16) * (KSTRIDE * 2)
                             + (kel + b_col_base) * 2;
                ldm4(bh[jp], Bh + off);
                ldm4(bl[jp], Bl + off);
            }
#pragma unroll
            for (int i = 0; i < 4; ++i)
#pragma unroll
                for (int j = 0; j < 4; ++j) {
                    const uint32_t* bhj = &bh[j >> 1][(j & 1) * 2];
                    const uint32_t* blj = &bl[j >> 1][(j & 1) * 2];
                    mma_bf16(acc[i][j], ah[i], bhj);
                    mma_bf16(acc[i][j], ah[i], blj);
                    mma_bf16(acc[i][j], al[i], bhj);
                }
        }
        __syncthreads();
        if (c + 2 < nchunk)
            issue_chunk(buf, row0, col0, k0 + (c + 2) * BK, tid);
        asm volatile("cp.async.commit_group;");
    }

    // Epilogue
    const int er = lane >> 2;                 // 0..7
    const int ec = (lane & 3) * 2;            // 0,2,4,6
#pragma unroll
    for (int i = 0; i < 4; ++i) {
#pragma unroll
        for (int j = 0; j < 4; ++j) {
            int r = row0 + wm * 64 + i * 16 + er;
            int cc = col0 + wn * 32 + j * 8 + ec;
            *reinterpret_cast<float2*>(C + (size_t)r * M_PTS + cc)
                = make_float2(acc[i][j][0], acc[i][j][1]);
            *reinterpret_cast<float2*>(C + (size_t)(r + 8) * M_PTS + cc)
                = make_float2(acc[i][j][2], acc[i][j][3]);
        }
    }
}

// ---------------------------------------------------------------------------
extern "C" void kernel_launch(void* const* d_in, const int* in_sizes, int n_in,
                              void* d_out, int out_size)
{
    const float* x    = (const float*)d_in[0];
    const float* grid = (const float*)d_in[1];
    const float* chol = (const float*)d_in[2];
    const float* ls   = (const float*)d_in[3];
    float* out = (float*)d_out;

    cudaFuncSetAttribute(gemm_hmma, cudaFuncAttributeMaxDynamicSharedMemorySize, SMEM_B);

    kstar_split<<<N_PTS, 256>>>(x, grid, ls);
    transpose_split<<<dim3(M_PTS / 32, M_PTS / 32), dim3(32, 8)>>>(chol);
    gemm_hmma<<<dim3(M_PTS / 128, N_PTS / 128), 256, SMEM_B>>>(out);
}

// round 5
// speedup vs baseline: 2.8154x; 1.1585x over previous
#include <cuda_runtime.h>
#include <cuda_bf16.h>
#include <cstdint>

// phi = exp(-sum_d |x[i,d]-g[j,d]|/ls[d]) @ chol_inv (lower-tri), [4096,4096] fp32.
// Engine: mma.sync bf16 (HMMA) hi/lo split x3, triangular K-start.
// R5: 64x64 warp tiles (4 warps/CTA) to cut ldmatrix smem traffic 33%.

#define N_PTS 4096
#define M_PTS 4096
#define DIMS 8

__device__ __nv_bfloat16 g_Ah[(size_t)N_PTS * M_PTS];
__device__ __nv_bfloat16 g_Al[(size_t)N_PTS * M_PTS];
__device__ __nv_bfloat16 g_Bh[(size_t)M_PTS * M_PTS];  // B^T: [j, k]
__device__ __nv_bfloat16 g_Bl[(size_t)M_PTS * M_PTS];

__device__ __forceinline__ uint32_t smem_u32(const void* p) {
    uint32_t a;
    asm("{ .reg .u64 t; cvta.to.shared.u64 t, %1; cvt.u32.u64 %0, t; }" : "=r"(a) : "l"(p));
    return a;
}

// ---------------------------------------------------------------------------
// Stage 1: k_star rows -> bf16 hi/lo  (exp2 path: fold 1/ln2 into recip-ls)
// ---------------------------------------------------------------------------
__global__ __launch_bounds__(256) void kstar_split(
    const float* __restrict__ x, const float* __restrict__ grid,
    const float* __restrict__ ls)
{
    const int i = blockIdx.x;
    __shared__ float xs[DIMS], rls[DIMS];
    if (threadIdx.x < DIMS) {
        xs[threadIdx.x]  = x[(size_t)i * DIMS + threadIdx.x];
        rls[threadIdx.x] = 1.442695040888963f / ls[threadIdx.x];
    }
    __syncthreads();
    float xr[DIMS], rl[DIMS];
#pragma unroll
    for (int d = 0; d < DIMS; d++) { xr[d] = xs[d]; rl[d] = rls[d]; }

    const float4* g4 = reinterpret_cast<const float4*>(grid);
    __nv_bfloat16* oh = g_Ah + (size_t)i * M_PTS;
    __nv_bfloat16* ol = g_Al + (size_t)i * M_PTS;

    for (int j = threadIdx.x; j < M_PTS; j += blockDim.x) {
        float4 a = g4[2 * j];
        float4 b = g4[2 * j + 1];
        float s = fabsf(xr[0] - a.x) * rl[0] + fabsf(xr[1] - a.y) * rl[1]
                + fabsf(xr[2] - a.z) * rl[2] + fabsf(xr[3] - a.w) * rl[3]
                + fabsf(xr[4] - b.x) * rl[4] + fabsf(xr[5] - b.y) * rl[5]
                + fabsf(xr[6] - b.z) * rl[6] + fabsf(xr[7] - b.w) * rl[7];
        float e = exp2f(-s);
        __nv_bfloat16 h = __float2bfloat16(e);
        float rem = e - __bfloat162float(h);
        oh[j] = h;
        ol[j] = __float2bfloat16(rem);
    }
}

// ---------------------------------------------------------------------------
// Stage 2: transpose chol -> B^T[j,k] bf16 hi/lo
// ---------------------------------------------------------------------------
__global__ __launch_bounds__(256) void transpose_split(const float* __restrict__ chol)
{
    __shared__ float t[32][33];
    const int tx = threadIdx.x, ty = threadIdx.y;   // (32, 8)
    const int j0 = blockIdx.x * 32, k0 = blockIdx.y * 32;
#pragma unroll
    for (int r = 0; r < 32; r += 8)
        t[ty + r][tx] = chol[(size_t)(k0 + ty + r) * M_PTS + j0 + tx];
    __syncthreads();
#pragma unroll
    for (int r = 0; r < 32; r += 8) {
        float v = t[tx][ty + r];
        __nv_bfloat16 h = __float2bfloat16(v);
        float rem = v - __bfloat162float(h);
        size_t o = (size_t)(j0 + ty + r) * M_PTS + k0 + tx;
        g_Bh[o] = h;
        g_Bl[o] = __float2bfloat16(rem);
    }
}

// ---------------------------------------------------------------------------
// Stage 3: HMMA GEMM. CTA tile 128x128, BK=32, 4 warps (warp tile 64x64),
// cp.async double-buffer, padded smem stride 40 elems (80B, conflict-free),
// 2 CTAs/SM.
// ---------------------------------------------------------------------------
#define BK 32
#define KSTRIDE 40
#define TILE_B (128 * KSTRIDE * 2)              // 10240 bytes
#define BUF_B (4 * TILE_B)                      // 40960
#define SMEM_B (2 * BUF_B)                      // 81920

__device__ __forceinline__ void ldm4(uint32_t* r, uint32_t addr) {
    asm volatile("ldmatrix.sync.aligned.m8n8.x4.shared.b16 {%0,%1,%2,%3}, [%4];"
                 : "=r"(r[0]), "=r"(r[1]), "=r"(r[2]), "=r"(r[3]) : "r"(addr));
}
__device__ __forceinline__ void mma_bf16(float* c, const uint32_t* a, const uint32_t* b) {
    asm volatile(
        "mma.sync.aligned.m16n8k16.row.col.f32.bf16.bf16.f32 "
        "{%0,%1,%2,%3}, {%4,%5,%6,%7}, {%8,%9}, {%0,%1,%2,%3};"
        : "+f"(c[0]), "+f"(c[1]), "+f"(c[2]), "+f"(c[3])
        : "r"(a[0]), "r"(a[1]), "r"(a[2]), "r"(a[3]), "r"(b[0]), "r"(b[1]));
}
__device__ __forceinline__ void cpasync16(uint32_t saddr, const void* gaddr) {
    asm volatile("cp.async.cg.shared.global [%0], [%1], 16;" :: "r"(saddr), "l"(gaddr));
}

__device__ __forceinline__ void issue_chunk(uint32_t buf, int row0, int col0, int k,
                                            int tid)
{
    const __nv_bfloat16* srcs[4] = {
        g_Ah + (size_t)row0 * M_PTS, g_Al + (size_t)row0 * M_PTS,
        g_Bh + (size_t)col0 * M_PTS, g_Bl + (size_t)col0 * M_PTS };
#pragma unroll
    for (int t = 0; t < 4; ++t) {
        uint32_t sb = buf + t * TILE_B;
        const __nv_bfloat16* src = srcs[t];
#pragma unroll
        for (int p = 0; p < 4; ++p) {          // 512 x 16B per tile / 128 thr
            int idx = p * 128 + tid;
            int row = idx >> 2;
            int seg = idx & 3;
            cpasync16(sb + row * (KSTRIDE * 2) + seg * 16,
                      src + (size_t)row * M_PTS + k + seg * 8);
        }
    }
}

__global__ __launch_bounds__(128, 2) void gemm_hmma(float* __restrict__ C)
{
    extern __shared__ char smem[];
    const uint32_t sb = smem_u32(smem);
    const int tid = threadIdx.x;
    const int lane = tid & 31, wid = tid >> 5;
    const int wm = wid >> 1;                  // 0..1 (64-row slabs)
    const int wn = wid & 1;                   // 0..1 (64-col slabs)

    const int row0 = blockIdx.y * 128;
    const int col0 = blockIdx.x * 128;
    const int k0 = col0;                      // triangular skip
    const int nchunk = (M_PTS - k0) / BK;     // >= 4

    float acc[4][8][4];
#pragma unroll
    for (int i = 0; i < 4; ++i)
#pragma unroll
        for (int j = 0; j < 8; ++j)
#pragma unroll
            for (int q = 0; q < 4; ++q) acc[i][j][q] = 0.0f;

    const int lr = lane & 7, lsel = lane >> 3;
    // A: matrices (m0-7,k0)(m8-15,k0)(m0-7,k8)(m8-15,k8)
    const int a_row_base = wm * 64 + lr + (lsel & 1) * 8;
    const int a_col_base = (lsel >> 1) * 8;
    // B: matrices (n0-7,k0)(n0-7,k8)(n8-15,k0)(n8-15,k8)
    const int b_row_base = wn * 64 + (lsel >> 1) * 8 + lr;
    const int b_col_base = (lsel & 1) * 8;

    issue_chunk(sb, row0, col0, k0, tid);
    asm volatile("cp.async.commit_group;");
    if (nchunk > 1) issue_chunk(sb + BUF_B, row0, col0, k0 + BK, tid);
    asm volatile("cp.async.commit_group;");

    for (int c = 0; c < nchunk; ++c) {
        asm volatile("cp.async.wait_group 1;");
        __syncthreads();
        const uint32_t buf = sb + (c & 1) * BUF_B;
        const uint32_t Ah = buf, Al = buf + TILE_B;
        const uint32_t Bh = buf + 2 * TILE_B, Bl = buf + 3 * TILE_B;

#pragma unroll
        for (int ks = 0; ks < 2; ++ks) {
            const int kel = ks * 16;
            uint32_t ah[4][4], al[4][4], bh[4][4], bl[4][4];
#pragma unroll
            for (int i = 0; i < 4; ++i) {
                uint32_t off = (a_row_base + i * 16) * (KSTRIDE * 2)
                             + (kel + a_col_base) * 2;
                ldm4(ah[i], Ah + off);
                ldm4(al[i], Al + off);
            }
#pragma unroll
            for (int jp = 0; jp < 4; ++jp) {
                uint32_t off = (b_row_base + jp * 16) * (KSTRIDE * 2)
                             + (kel + b_col_base) * 2;
                ldm4(bh[jp], Bh + off);
                ldm4(bl[jp], Bl + off);
            }
#pragma unroll
            for (int i = 0; i < 4; ++i)
#pragma unroll
                for (int j = 0; j < 8; ++j) {
                    const uint32_t* bhj = &bh[j >> 1][(j & 1) * 2];
                    const uint32_t* blj = &bl[j >> 1][(j & 1) * 2];
                    mma_bf16(acc[i][j], ah[i], bhj);
                    mma_bf16(acc[i][j], ah[i], blj);
                    mma_bf16(acc[i][j], al[i], bhj);
                }
        }
        __syncthreads();
        if (c + 2 < nchunk)
            issue_chunk(buf, row0, col0, k0 + (c + 2) * BK, tid);
        asm volatile("cp.async.commit_group;");
    }

    // Epilogue
    const int er = lane >> 2;
    const int ec = (lane & 3) * 2;
#pragma unroll
    for (int i = 0; i < 4; ++i) {
#pragma unroll
        for (int j = 0; j < 8; ++j) {
            int r = row0 + wm * 64 + i * 16 + er;
            int cc = col0 + wn * 64 + j * 8 + ec;
            *reinterpret_cast<float2*>(C + (size_t)r * M_PTS + cc)
                = make_float2(acc[i][j][0], acc[i][j][1]);
            *reinterpret_cast<float2*>(C + (size_t)(r + 8) * M_PTS + cc)
                = make_float2(acc[i][j][2], acc[i][j][3]);
        }
    }
}

// ---------------------------------------------------------------------------
extern "C" void kernel_launch(void* const* d_in, const int* in_sizes, int n_in,
                              void* d_out, int out_size)
{
    const float* x    = (const float*)d_in[0];
    const float* grid = (const float*)d_in[1];
    const float* chol = (const float*)d_in[2];
    const float* ls   = (const float*)d_in[3];
    float* out = (float*)d_out;

    cudaFuncSetAttribute(gemm_hmma, cudaFuncAttributeMaxDynamicSharedMemorySize, SMEM_B);

    kstar_split<<<N_PTS, 256>>>(x, grid, ls);
    transpose_split<<<dim3(M_PTS / 32, M_PTS / 32), dim3(32, 8)>>>(chol);
    gemm_hmma<<<dim3(M_PTS / 128, N_PTS / 128), 128, SMEM_B>>>(out);
}